// round 2
// baseline (speedup 1.0000x reference)
#include <cuda_runtime.h>
#include <math.h>

#define S 2048
#define H 16
#define DK 64
#define DM 1024

// Scratch (allocation-free rule: __device__ globals)
__device__ float g_q [H*S*DK];
__device__ float g_k [H*S*DK];
__device__ float g_v [H*S*DK];
__device__ float g_br[H*S*DK];
__device__ float g_sin[S*32];
__device__ float g_cos[S*32];
__device__ unsigned char g_mask[S];

// ---------------------------------------------------------------------------
// Packed fp32x2 helpers (sm_103a FFMA2 path — only reachable via PTX)
// ---------------------------------------------------------------------------
typedef unsigned long long u64;

__device__ __forceinline__ u64 fma2(u64 a, u64 b, u64 c) {
    u64 d;
    asm("fma.rn.f32x2 %0, %1, %2, %3;" : "=l"(d) : "l"(a), "l"(b), "l"(c));
    return d;
}
__device__ __forceinline__ u64 add2(u64 a, u64 b) {
    u64 d;
    asm("add.rn.f32x2 %0, %1, %2;" : "=l"(d) : "l"(a), "l"(b));
    return d;
}
__device__ __forceinline__ u64 pack2(float lo, float hi) {
    u64 d;
    asm("mov.b64 %0, {%1, %2};" : "=l"(d) : "f"(lo), "f"(hi));
    return d;
}
__device__ __forceinline__ float2 unpack2(u64 v) {
    float lo, hi;
    asm("mov.b64 {%0, %1}, %2;" : "=f"(lo), "=f"(hi) : "l"(v));
    return make_float2(lo, hi);
}

// ---------------------------------------------------------------------------
// RoPE sin/cos table. Angle computed exactly as reference (fp32 n * fp32
// inv_freq), trig evaluated in double for accuracy.
// ---------------------------------------------------------------------------
__global__ void rope_table_k()
{
    int idx = blockIdx.x * 256 + threadIdx.x;
    if (idx >= S * 32) return;
    int n = idx >> 5, i = idx & 31;
    double invf_d = exp(-((double)i / 32.0) * log(10000.0));
    float  invf   = (float)invf_d;
    float  ang    = (float)n * invf;       // fp32, matching reference
    double a      = (double)ang;
    g_sin[idx] = (float)sin(a);
    g_cos[idx] = (float)cos(a);
}

// ---------------------------------------------------------------------------
// Mask normalization: detect bool(1B) vs int32(4B) storage, write uchar mask.
// ---------------------------------------------------------------------------
__global__ void mask_norm_k(const unsigned char* __restrict__ mraw)
{
    __shared__ int is_bool;
    if (threadIdx.x == 0) is_bool = 0;
    __syncthreads();
    int f = 0;
    for (int i = threadIdx.x; i < S; i += 256)
        if ((i & 3) != 0 && mraw[i] != 0) f = 1;
    if (f) atomicExch(&is_bool, 1);
    __syncthreads();
    if (is_bool) {
        for (int i = threadIdx.x; i < S; i += 256)
            g_mask[i] = mraw[i] ? 1 : 0;
    } else {
        const int* mi = (const int*)mraw;
        for (int i = threadIdx.x; i < S; i += 256)
            g_mask[i] = mi[i] ? 1 : 0;
    }
}

// ---------------------------------------------------------------------------
// Fused projection SGEMM with FFMA2: out = X @ W for 4 (X, W) pairs.
// M=2048, N=1024, K=1024. 128x128 tile, 256 threads, 8x8 microtile,
// k-depth 16 with register prefetch (double buffer in regs).
// Output stored head-major: O[h][n][dk].
// ---------------------------------------------------------------------------
__global__ __launch_bounds__(256) void proj_k(
    const float* __restrict__ Xq, const float* __restrict__ Xk,
    const float* __restrict__ Xv, const float* __restrict__ Xb,
    const float* __restrict__ LL, const float* __restrict__ BP)
{
    __shared__ __align__(16) float As[16][132];   // [k][m]
    __shared__ __align__(16) float Bs[16][128];   // [k][n]

    int which = blockIdx.z;
    const float* X = (which == 0) ? Xq : (which == 1) ? Xk : (which == 2) ? Xv : Xb;
    const float* W = (which < 3) ? (LL + (size_t)which * DM * DM) : BP;
    float* O = (which == 0) ? g_q : (which == 1) ? g_k : (which == 2) ? g_v : g_br;

    int tid = threadIdx.x;
    int tx = tid & 15, ty = tid >> 4;
    int m0 = blockIdx.y * 128, n0 = blockIdx.x * 128;

    // acc2[i][j2]: row i (0..7), paired columns j2: {c0c1, c2c3, c64+0/1, c64+2/3}
    u64 acc2[8][4];
#pragma unroll
    for (int i = 0; i < 8; i++)
#pragma unroll
        for (int j = 0; j < 4; j++) acc2[i][j] = 0ULL;

    int lm = tid >> 1;            // A load: row within tile (0..127)
    int lq = (tid & 1) * 4;       // A load: k-quad (0 or 4)
    int lk = tid >> 5;            // B load: k row (0..7)
    int lc = (tid & 31) * 4;      // B load: col

    // prefetch first k-block into regs
    float4 pa0 = *(const float4*)&X[(size_t)(m0 + lm) * DM + lq];
    float4 pa1 = *(const float4*)&X[(size_t)(m0 + lm) * DM + lq + 8];
    float4 pb0 = *(const float4*)&W[(size_t)lk * DM + n0 + lc];
    float4 pb1 = *(const float4*)&W[(size_t)(lk + 8) * DM + n0 + lc];

    for (int k0 = 0; k0 < DM; k0 += 16) {
        As[lq + 0][lm] = pa0.x; As[lq + 1][lm] = pa0.y;
        As[lq + 2][lm] = pa0.z; As[lq + 3][lm] = pa0.w;
        As[lq + 8][lm] = pa1.x; As[lq + 9][lm] = pa1.y;
        As[lq +10][lm] = pa1.z; As[lq +11][lm] = pa1.w;
        *(float4*)&Bs[lk][lc]     = pb0;
        *(float4*)&Bs[lk + 8][lc] = pb1;
        __syncthreads();

        if (k0 + 16 < DM) {   // prefetch next k-block (LDG in flight over compute)
            pa0 = *(const float4*)&X[(size_t)(m0 + lm) * DM + k0 + 16 + lq];
            pa1 = *(const float4*)&X[(size_t)(m0 + lm) * DM + k0 + 16 + lq + 8];
            pb0 = *(const float4*)&W[(size_t)(k0 + 16 + lk) * DM + n0 + lc];
            pb1 = *(const float4*)&W[(size_t)(k0 + 16 + lk + 8) * DM + n0 + lc];
        }

#pragma unroll
        for (int kk = 0; kk < 16; kk++) {
            float4 t0 = *(const float4*)&As[kk][ty * 8];
            float4 t1 = *(const float4*)&As[kk][ty * 8 + 4];
            ulonglong2 u0 = *(const ulonglong2*)&Bs[kk][tx * 4];
            ulonglong2 u1 = *(const ulonglong2*)&Bs[kk][64 + tx * 4];
            float av[8] = {t0.x, t0.y, t0.z, t0.w, t1.x, t1.y, t1.z, t1.w};
#pragma unroll
            for (int i = 0; i < 8; i++) {
                u64 a2 = pack2(av[i], av[i]);
                acc2[i][0] = fma2(a2, u0.x, acc2[i][0]);
                acc2[i][1] = fma2(a2, u0.y, acc2[i][1]);
                acc2[i][2] = fma2(a2, u1.x, acc2[i][2]);
                acc2[i][3] = fma2(a2, u1.y, acc2[i][3]);
            }
        }
        __syncthreads();
    }

#pragma unroll
    for (int i = 0; i < 8; i++) {
        int m  = m0 + ty * 8 + i;
        int cA = n0 + tx * 4;
        int cB = n0 + 64 + tx * 4;
        float2 p0 = unpack2(acc2[i][0]), p1 = unpack2(acc2[i][1]);
        float2 p2 = unpack2(acc2[i][2]), p3 = unpack2(acc2[i][3]);
        float4 r0 = make_float4(p0.x, p0.y, p1.x, p1.y);
        float4 r1 = make_float4(p2.x, p2.y, p3.x, p3.y);
        *(float4*)&O[((size_t)(cA >> 6) << 17) + (size_t)m * DK + (cA & 63)] = r0;
        *(float4*)&O[((size_t)(cB >> 6) << 17) + (size_t)m * DK + (cB & 63)] = r1;
    }
}

// ---------------------------------------------------------------------------
// RoPE + b_rotate applied in place to g_q and g_k.
// ---------------------------------------------------------------------------
__global__ void rope_apply_k()
{
    int idx = blockIdx.x * 256 + threadIdx.x;
    if (idx >= 2 * H * S * 32) return;
    int i = idx & 31;
    int n = (idx >> 5) & (S - 1);
    int h = (idx >> 16) & (H - 1);
    int which = idx >> 20;

    float* buf = which ? g_k : g_q;
    size_t base = ((size_t)h << 17) + (size_t)n * DK;
    float x1 = buf[base + 2 * i];
    float x2 = buf[base + 2 * i + 1];
    float sn = g_sin[n * 32 + i];
    float cs = g_cos[n * 32 + i];
    float e = x1 * cs - x2 * sn;
    float o = x1 * sn + x2 * cs;
    buf[base + 2 * i]     = e * g_br[base + 2 * i];
    buf[base + 2 * i + 1] = o * g_br[base + 2 * i + 1];
}

// ---------------------------------------------------------------------------
// Flash attention with FFMA2 + __expf + warp-uniform PV skip.
// One thread per query row, 128-row q tiles, 64-row K/V tiles in shared.
// ---------------------------------------------------------------------------
__global__ __launch_bounds__(128) void attn_k(float* __restrict__ out)
{
    __shared__ __align__(16) float Ks[64][64];
    __shared__ __align__(16) float Vs[64][64];
    __shared__ unsigned char ms[64];

    int h = blockIdx.y;
    int r = blockIdx.x * 128 + threadIdx.x;
    const float* qp = g_q + ((size_t)h << 17) + (size_t)r * DK;
    const float* kb = g_k + ((size_t)h << 17);
    const float* vb = g_v + ((size_t)h << 17);

    // q row, scaled by 1/sqrt(64), packed into 32 fp32x2 pairs
    u64 qr2[32];
#pragma unroll
    for (int t = 0; t < 16; t++) {
        float4 q4 = *(const float4*)&qp[t * 4];
        qr2[t * 2 + 0] = pack2(q4.x * 0.125f, q4.y * 0.125f);
        qr2[t * 2 + 1] = pack2(q4.z * 0.125f, q4.w * 0.125f);
    }

    bool mq = g_mask[r] != 0;
    float mrun = -INFINITY, l = 0.f;
    u64 acc2[32];
#pragma unroll
    for (int t = 0; t < 32; t++) acc2[t] = 0ULL;

    for (int kt = 0; kt < 32; kt++) {
        int kbase = kt * 64;
        {
            int jr  = threadIdx.x >> 1;
            int col = (threadIdx.x & 1) * 32;
            const float4* ksrc = (const float4*)(kb + (size_t)(kbase + jr) * 64 + col);
            const float4* vsrc = (const float4*)(vb + (size_t)(kbase + jr) * 64 + col);
            float4* kd = (float4*)&Ks[jr][col];
            float4* vd = (float4*)&Vs[jr][col];
#pragma unroll
            for (int i = 0; i < 8; i++) { kd[i] = ksrc[i]; vd[i] = vsrc[i]; }
            if (threadIdx.x < 64) ms[threadIdx.x] = g_mask[kbase + threadIdx.x];
        }
        __syncthreads();

        for (int j = 0; j < 64; j++) {
            float s;
            if (mq && (ms[j] != 0)) {
                const ulonglong2* k2 = (const ulonglong2*)&Ks[j][0];
                u64 sa = 0ULL, sb = 0ULL, sc = 0ULL, sd = 0ULL;
#pragma unroll
                for (int t = 0; t < 8; t++) {
                    ulonglong2 ka = k2[t * 2];
                    ulonglong2 kc = k2[t * 2 + 1];
                    sa = fma2(qr2[t * 4 + 0], ka.x, sa);
                    sb = fma2(qr2[t * 4 + 1], ka.y, sb);
                    sc = fma2(qr2[t * 4 + 2], kc.x, sc);
                    sd = fma2(qr2[t * 4 + 3], kc.y, sd);
                }
                sa = add2(sa, sb);
                sc = add2(sc, sd);
                sa = add2(sa, sc);
                float2 f = unpack2(sa);
                s = f.x + f.y;
            } else {
                s = -1e30f;
            }

            bool upd  = s > mrun;
            // p = exp(s-mrun) < 1e-13 contributes < 1e-10 relative — skip when
            // the whole warp agrees (saves PV FMAs + V LDS).
            bool skip = (!upd) && (s - mrun < -30.f);
            if (__all_sync(0xffffffffu, skip)) continue;

            const ulonglong2* v2p = (const ulonglong2*)&Vs[j][0];
            if (!upd) {
                float p = __expf(s - mrun);
                l += p;
                u64 p2 = pack2(p, p);
#pragma unroll
                for (int t = 0; t < 16; t++) {
                    ulonglong2 vv = v2p[t];
                    acc2[t * 2 + 0] = fma2(p2, vv.x, acc2[t * 2 + 0]);
                    acc2[t * 2 + 1] = fma2(p2, vv.y, acc2[t * 2 + 1]);
                }
            } else {
                float corr = __expf(mrun - s);   // first hit: __expf(-inf)=0
                mrun = s;
                l = l * corr + 1.f;
                u64 c2 = pack2(corr, corr);
#pragma unroll
                for (int t = 0; t < 16; t++) {
                    ulonglong2 vv = v2p[t];
                    acc2[t * 2 + 0] = fma2(acc2[t * 2 + 0], c2, vv.x);
                    acc2[t * 2 + 1] = fma2(acc2[t * 2 + 1], c2, vv.y);
                }
            }
        }
        __syncthreads();
    }

    float inv = 1.f / l;
    float* op = out + (size_t)r * DM + h * DK;
#pragma unroll
    for (int t = 0; t < 8; t++) {
        float2 e0 = unpack2(acc2[t * 4 + 0]);
        float2 e1 = unpack2(acc2[t * 4 + 1]);
        float2 e2 = unpack2(acc2[t * 4 + 2]);
        float2 e3 = unpack2(acc2[t * 4 + 3]);
        float4 o0 = make_float4(e0.x * inv, e0.y * inv, e1.x * inv, e1.y * inv);
        float4 o1 = make_float4(e2.x * inv, e2.y * inv, e3.x * inv, e3.y * inv);
        *(float4*)&op[t * 8]     = o0;
        *(float4*)&op[t * 8 + 4] = o1;
    }
}

// ---------------------------------------------------------------------------
extern "C" void kernel_launch(void* const* d_in, const int* in_sizes, int n_in,
                              void* d_out, int out_size)
{
    const float* query = (const float*)d_in[0];
    const float* key   = (const float*)d_in[1];
    const float* value = (const float*)d_in[2];
    const float* b_emb = (const float*)d_in[3];
    const unsigned char* mraw = (const unsigned char*)d_in[4];
    const float* LL    = (const float*)d_in[5];
    const float* BP    = (const float*)d_in[6];
    float* out = (float*)d_out;

    rope_table_k<<<(S * 32 + 255) / 256, 256>>>();
    mask_norm_k<<<1, 256>>>(mraw);
    proj_k<<<dim3(8, 16, 4), 256>>>(query, key, value, b_emb, LL, BP);
    rope_apply_k<<<(2 * H * S * 32 + 255) / 256, 256>>>();
    attn_k<<<dim3(16, 16), 128>>>(out);
}

// round 3
// speedup vs baseline: 1.9319x; 1.9319x over previous
#include <cuda_runtime.h>
#include <math.h>

#define S 2048
#define H 16
#define DK 64
#define DM 1024

// Scratch (allocation-free rule: __device__ globals)
__device__ float g_q [H*S*DK];
__device__ float g_k [H*S*DK];
__device__ float g_v [H*S*DK];
__device__ float g_br[H*S*DK];
__device__ float g_vmean[H*DK];
__device__ float g_sin[S*32];
__device__ float g_cos[S*32];
__device__ unsigned char g_mask[S];

// ---------------------------------------------------------------------------
// RoPE sin/cos table. Angle computed exactly as reference (fp32 n * fp32
// inv_freq), trig evaluated in double for accuracy.
// ---------------------------------------------------------------------------
__global__ void rope_table_k()
{
    int idx = blockIdx.x * 256 + threadIdx.x;
    if (idx >= S * 32) return;
    int n = idx >> 5, i = idx & 31;
    double invf_d = exp(-((double)i / 32.0) * log(10000.0));
    float  invf   = (float)invf_d;
    float  ang    = (float)n * invf;       // fp32, matching reference
    double a      = (double)ang;
    g_sin[idx] = (float)sin(a);
    g_cos[idx] = (float)cos(a);
}

// ---------------------------------------------------------------------------
// Mask normalization: detect bool(1B) vs int32(4B) storage, write uchar mask.
// ---------------------------------------------------------------------------
__global__ void mask_norm_k(const unsigned char* __restrict__ mraw)
{
    __shared__ int is_bool;
    if (threadIdx.x == 0) is_bool = 0;
    __syncthreads();
    int f = 0;
    for (int i = threadIdx.x; i < S; i += 256)
        if ((i & 3) != 0 && mraw[i] != 0) f = 1;
    if (f) atomicExch(&is_bool, 1);
    __syncthreads();
    if (is_bool) {
        for (int i = threadIdx.x; i < S; i += 256)
            g_mask[i] = mraw[i] ? 1 : 0;
    } else {
        const int* mi = (const int*)mraw;
        for (int i = threadIdx.x; i < S; i += 256)
            g_mask[i] = mi[i] ? 1 : 0;
    }
}

// ---------------------------------------------------------------------------
// Per-head column mean of V (masked query rows output exactly mean(V):
// reference softmax over all-NEG_INF scores is uniform over all 2048 keys).
// ---------------------------------------------------------------------------
__global__ void vmean_k()
{
    __shared__ float red[256];
    int h = blockIdx.x;
    int t = threadIdx.x;
    int col = t & 63;
    int seg = t >> 6;           // 0..3
    const float* vb = g_v + ((size_t)h << 17);
    float s = 0.f;
    for (int r = seg * 512; r < (seg + 1) * 512; r++)
        s += vb[(size_t)r * DK + col];
    red[t] = s;
    __syncthreads();
    if (t < 64)
        g_vmean[h * DK + t] = (red[t] + red[t + 64] + red[t + 128] + red[t + 192])
                              * (1.f / 2048.f);
}

// ---------------------------------------------------------------------------
// Fused projection SGEMM: out = X @ W for 4 (X, W) pairs (blockIdx.z).
// M=2048, N=1024, K=1024. 128x128 tile, 256 threads, 8x8 microtile,
// k-depth 16 with register prefetch. Output stored head-major: O[h][n][dk].
// ---------------------------------------------------------------------------
__global__ __launch_bounds__(256) void proj_k(
    const float* __restrict__ Xq, const float* __restrict__ Xk,
    const float* __restrict__ Xv, const float* __restrict__ Xb,
    const float* __restrict__ LL, const float* __restrict__ BP)
{
    __shared__ __align__(16) float As[16][132];   // [k][m]
    __shared__ __align__(16) float Bs[16][128];   // [k][n]

    int which = blockIdx.z;
    const float* X = (which == 0) ? Xq : (which == 1) ? Xk : (which == 2) ? Xv : Xb;
    const float* W = (which < 3) ? (LL + (size_t)which * DM * DM) : BP;
    float* O = (which == 0) ? g_q : (which == 1) ? g_k : (which == 2) ? g_v : g_br;

    int tid = threadIdx.x;
    int tx = tid & 15, ty = tid >> 4;
    int m0 = blockIdx.y * 128, n0 = blockIdx.x * 128;

    float acc[8][8];
#pragma unroll
    for (int i = 0; i < 8; i++)
#pragma unroll
        for (int j = 0; j < 8; j++) acc[i][j] = 0.f;

    int lm = tid >> 1;            // A load: row within tile (0..127)
    int lq = (tid & 1) * 4;       // A load: k-quad (0 or 4)
    int lk = tid >> 5;            // B load: k row (0..7)
    int lc = (tid & 31) * 4;      // B load: col

    // prefetch first k-block into regs
    float4 pa0 = *(const float4*)&X[(size_t)(m0 + lm) * DM + lq];
    float4 pa1 = *(const float4*)&X[(size_t)(m0 + lm) * DM + lq + 8];
    float4 pb0 = *(const float4*)&W[(size_t)lk * DM + n0 + lc];
    float4 pb1 = *(const float4*)&W[(size_t)(lk + 8) * DM + n0 + lc];

    for (int k0 = 0; k0 < DM; k0 += 16) {
        As[lq + 0][lm] = pa0.x; As[lq + 1][lm] = pa0.y;
        As[lq + 2][lm] = pa0.z; As[lq + 3][lm] = pa0.w;
        As[lq + 8][lm] = pa1.x; As[lq + 9][lm] = pa1.y;
        As[lq +10][lm] = pa1.z; As[lq +11][lm] = pa1.w;
        *(float4*)&Bs[lk][lc]     = pb0;
        *(float4*)&Bs[lk + 8][lc] = pb1;
        __syncthreads();

        if (k0 + 16 < DM) {   // next k-block LDGs in flight over compute
            pa0 = *(const float4*)&X[(size_t)(m0 + lm) * DM + k0 + 16 + lq];
            pa1 = *(const float4*)&X[(size_t)(m0 + lm) * DM + k0 + 16 + lq + 8];
            pb0 = *(const float4*)&W[(size_t)(k0 + 16 + lk) * DM + n0 + lc];
            pb1 = *(const float4*)&W[(size_t)(k0 + 16 + lk + 8) * DM + n0 + lc];
        }

#pragma unroll
        for (int kk = 0; kk < 16; kk++) {
            float a[8], b[8];
            float4 t0 = *(const float4*)&As[kk][ty * 8];
            float4 t1 = *(const float4*)&As[kk][ty * 8 + 4];
            a[0]=t0.x; a[1]=t0.y; a[2]=t0.z; a[3]=t0.w;
            a[4]=t1.x; a[5]=t1.y; a[6]=t1.z; a[7]=t1.w;
            float4 u0 = *(const float4*)&Bs[kk][tx * 4];
            float4 u1 = *(const float4*)&Bs[kk][64 + tx * 4];
            b[0]=u0.x; b[1]=u0.y; b[2]=u0.z; b[3]=u0.w;
            b[4]=u1.x; b[5]=u1.y; b[6]=u1.z; b[7]=u1.w;
#pragma unroll
            for (int i = 0; i < 8; i++)
#pragma unroll
                for (int j = 0; j < 8; j++) acc[i][j] += a[i] * b[j];
        }
        __syncthreads();
    }

#pragma unroll
    for (int i = 0; i < 8; i++) {
        int m  = m0 + ty * 8 + i;
        int cA = n0 + tx * 4;
        int cB = n0 + 64 + tx * 4;
        float4 r0 = make_float4(acc[i][0], acc[i][1], acc[i][2], acc[i][3]);
        float4 r1 = make_float4(acc[i][4], acc[i][5], acc[i][6], acc[i][7]);
        *(float4*)&O[((size_t)(cA >> 6) << 17) + (size_t)m * DK + (cA & 63)] = r0;
        *(float4*)&O[((size_t)(cB >> 6) << 17) + (size_t)m * DK + (cB & 63)] = r1;
    }
}

// ---------------------------------------------------------------------------
// RoPE + b_rotate applied in place to g_q and g_k.
// ---------------------------------------------------------------------------
__global__ void rope_apply_k()
{
    int idx = blockIdx.x * 256 + threadIdx.x;
    if (idx >= 2 * H * S * 32) return;
    int i = idx & 31;
    int n = (idx >> 5) & (S - 1);
    int h = (idx >> 16) & (H - 1);
    int which = idx >> 20;

    float* buf = which ? g_k : g_q;
    size_t base = ((size_t)h << 17) + (size_t)n * DK;
    float x1 = buf[base + 2 * i];
    float x2 = buf[base + 2 * i + 1];
    float sn = g_sin[n * 32 + i];
    float cs = g_cos[n * 32 + i];
    float e = x1 * cs - x2 * sn;
    float o = x1 * sn + x2 * cs;
    buf[base + 2 * i]     = e * g_br[base + 2 * i];
    buf[base + 2 * i + 1] = o * g_br[base + 2 * i + 1];
}

// ---------------------------------------------------------------------------
// Flash attention. One thread per query row, 128-row q tiles, 64-row K/V
// tiles in shared. Online softmax, __expf, PV skip (scores are near-one-hot:
// keys more than 25 below the running max contribute < 1e-9 relative).
// Masked query rows bypass the loop entirely and emit mean(V).
// Masked key columns are skipped warp-uniformly (ms[j] is lane-invariant).
// ---------------------------------------------------------------------------
__global__ __launch_bounds__(128) void attn_k(float* __restrict__ out)
{
    __shared__ __align__(16) float Ks[64][64];
    __shared__ __align__(16) float Vs[64][64];
    __shared__ unsigned char ms[64];

    int h = blockIdx.y;
    int r = blockIdx.x * 128 + threadIdx.x;
    const float* qp = g_q + ((size_t)h << 17) + (size_t)r * DK;
    const float* kb = g_k + ((size_t)h << 17);
    const float* vb = g_v + ((size_t)h << 17);

    float qr[64];
#pragma unroll
    for (int d = 0; d < 64; d++) qr[d] = qp[d] * 0.125f;   // fold 1/sqrt(64)

    bool mq = g_mask[r] != 0;
    float mrun = -INFINITY, l = 0.f;
    float acc[64];
#pragma unroll
    for (int d = 0; d < 64; d++) acc[d] = 0.f;

    for (int kt = 0; kt < 32; kt++) {
        int kbase = kt * 64;
        {
            int jr  = threadIdx.x >> 1;
            int col = (threadIdx.x & 1) * 32;
            const float4* ksrc = (const float4*)(kb + (size_t)(kbase + jr) * 64 + col);
            const float4* vsrc = (const float4*)(vb + (size_t)(kbase + jr) * 64 + col);
            float4* kd = (float4*)&Ks[jr][col];
            float4* vd = (float4*)&Vs[jr][col];
#pragma unroll
            for (int i = 0; i < 8; i++) { kd[i] = ksrc[i]; vd[i] = vsrc[i]; }
            if (threadIdx.x < 64) ms[threadIdx.x] = g_mask[kbase + threadIdx.x];
        }
        __syncthreads();

        for (int j = 0; j < 64; j++) {
            if (ms[j] == 0) continue;            // warp-uniform key skip

            // QK dot (meaningful only for unmasked-row lanes)
            const float4* k4 = (const float4*)&Ks[j][0];
            float s0 = 0.f, s1 = 0.f, s2 = 0.f, s3 = 0.f;
#pragma unroll
            for (int d4 = 0; d4 < 16; d4++) {
                float4 kv = k4[d4];
                s0 += qr[d4 * 4 + 0] * kv.x;
                s1 += qr[d4 * 4 + 1] * kv.y;
                s2 += qr[d4 * 4 + 2] * kv.z;
                s3 += qr[d4 * 4 + 3] * kv.w;
            }
            float s = (s0 + s1) + (s2 + s3);
            float d = s - mrun;                  // mrun=-inf on first hit -> +inf

            if (mq && d > -25.f) {               // rare: ~17% of keys warp-wide
                const float4* v4 = (const float4*)&Vs[j][0];
                if (d <= 0.f) {
                    float p = __expf(d);
                    l += p;
#pragma unroll
                    for (int d4 = 0; d4 < 16; d4++) {
                        float4 vv = v4[d4];
                        acc[d4 * 4 + 0] += p * vv.x;
                        acc[d4 * 4 + 1] += p * vv.y;
                        acc[d4 * 4 + 2] += p * vv.z;
                        acc[d4 * 4 + 3] += p * vv.w;
                    }
                } else {
                    float corr = __expf(-d);     // first hit: __expf(-inf)=0
                    mrun = s;
                    l = l * corr + 1.f;
#pragma unroll
                    for (int d4 = 0; d4 < 16; d4++) {
                        float4 vv = v4[d4];
                        acc[d4 * 4 + 0] = acc[d4 * 4 + 0] * corr + vv.x;
                        acc[d4 * 4 + 1] = acc[d4 * 4 + 1] * corr + vv.y;
                        acc[d4 * 4 + 2] = acc[d4 * 4 + 2] * corr + vv.z;
                        acc[d4 * 4 + 3] = acc[d4 * 4 + 3] * corr + vv.w;
                    }
                }
            }
        }
        __syncthreads();
    }

    float* op = out + (size_t)r * DM + h * DK;
    if (mq) {
        float inv = 1.f / l;
#pragma unroll
        for (int d4 = 0; d4 < 16; d4++) {
            float4 o4 = make_float4(acc[d4 * 4 + 0] * inv, acc[d4 * 4 + 1] * inv,
                                    acc[d4 * 4 + 2] * inv, acc[d4 * 4 + 3] * inv);
            *(float4*)&op[d4 * 4] = o4;
        }
    } else {
        const float4* vm = (const float4*)&g_vmean[h * DK];
#pragma unroll
        for (int d4 = 0; d4 < 16; d4++)
            *(float4*)&op[d4 * 4] = vm[d4];
    }
}

// ---------------------------------------------------------------------------
extern "C" void kernel_launch(void* const* d_in, const int* in_sizes, int n_in,
                              void* d_out, int out_size)
{
    const float* query = (const float*)d_in[0];
    const float* key   = (const float*)d_in[1];
    const float* value = (const float*)d_in[2];
    const float* b_emb = (const float*)d_in[3];
    const unsigned char* mraw = (const unsigned char*)d_in[4];
    const float* LL    = (const float*)d_in[5];
    const float* BP    = (const float*)d_in[6];
    float* out = (float*)d_out;

    rope_table_k<<<(S * 32 + 255) / 256, 256>>>();
    mask_norm_k<<<1, 256>>>(mraw);
    proj_k<<<dim3(8, 16, 4), 256>>>(query, key, value, b_emb, LL, BP);
    vmean_k<<<16, 256>>>();
    rope_apply_k<<<(2 * H * S * 32 + 255) / 256, 256>>>();
    attn_k<<<dim3(16, 16), 128>>>(out);
}